// round 14
// baseline (speedup 1.0000x reference)
#include <cuda_runtime.h>
#include <cstdint>

// Problem constants
#define BQ 16
#define DQ 128
#define TQ 4096
#define VQ 1024

#define TILE_M 128
#define TILE_N 128
#define NCHUNK 8
#define QCAP 4096
#define NTHREADS 512

// Dynamic SMEM layout (bytes)
#define OFF_RES     0          // 128 x u64 packed (score,idx)
#define OFF_ROWMIN  1024       // 128 x u32
#define OFF_QN      1536       // u32 queue counter
#define OFF_MARG    1600       // 128 floats: per-row margin (SX during load)
#define OFF_TILEMAX 2112       // u32 (abs-max of x tile, float bits)
#define OFF_CSQ     2176       // 1024 floats
#define OFF_QUEUE   6272       // QCAP x u32 (16KB)
#define OFF_AF      22656      // fp32 A [128][AF_STRIDE]
#define AF_STRIDE   132
#define OFF_A8      90240      // int8 A tile 16KB (swizzled, 128B rows)
#define OFF_B       106624     // int8 B tiles, 2 x 16KB (double buffer)
#define BTILE       16384
#define SMEM_TOTAL  139392

__device__ float g_csq[VQ];
__device__ float g_cabrow[VQ];   // per-row sum|c|
__device__ float g_cmaxrow[VQ];  // per-row max|c|
__device__ float g_sc;           // codebook scale = max|c|/127
__device__ float g_cab;          // max_v sum|c|
__device__ signed char g_ci8[VQ * DQ];

// ---------------------------------------------------------------------------
__device__ __forceinline__ uint32_t smem_u32(const void* p) {
    uint32_t a;
    asm("{ .reg .u64 t; cvta.to.shared.u64 t, %1; cvt.u32.u64 %0, t; }"
        : "=r"(a) : "l"(p));
    return a;
}

#define LDMX4(r, addr) \
    asm volatile("ldmatrix.sync.aligned.m8n8.x4.shared.b16 {%0,%1,%2,%3}, [%4];" \
        : "=r"((r)[0]), "=r"((r)[1]), "=r"((r)[2]), "=r"((r)[3]) \
        : "r"(addr))

__device__ __forceinline__ void mma_s8(int* c, const uint32_t* a,
                                       const uint32_t* b) {
    asm volatile(
        "mma.sync.aligned.m16n8k32.row.col.s32.s8.s8.s32 "
        "{%0,%1,%2,%3}, {%4,%5,%6,%7}, {%8,%9}, {%0,%1,%2,%3};"
        : "+r"(c[0]), "+r"(c[1]), "+r"(c[2]), "+r"(c[3])
        : "r"(a[0]), "r"(a[1]), "r"(a[2]), "r"(a[3]), "r"(b[0]), "r"(b[1]));
}

#define CP_ASYNC16(dst, src) \
    asm volatile("cp.async.cg.shared.global [%0], [%1], 16;" \
        :: "r"(dst), "l"(src))
#define CP_COMMIT() asm volatile("cp.async.commit_group;" ::: "memory")
#define CP_WAIT1() asm volatile("cp.async.wait_group 1;" ::: "memory")
#define CP_WAIT0() asm volatile("cp.async.wait_group 0;" ::: "memory")

// Swizzled byte offset inside a (rows x 128) INT8 tile: 128B rows, 16B
// chunks, chunk column XOR'd with row%8 -> conflict-free ldmatrix.
// (Validated by R10's rel_err = 0.0.)
__device__ __forceinline__ uint32_t tswz8(int row, int chunk) {
    return (uint32_t)(row * 128 + ((chunk ^ (row & 7)) << 4));
}

// Order-preserving float <-> uint
__device__ __forceinline__ unsigned fford(float f) {
    unsigned u = __float_as_uint(f);
    return (u & 0x80000000u) ? ~u : (u | 0x80000000u);
}
__device__ __forceinline__ float fford_inv(unsigned u) {
    unsigned b = (u & 0x80000000u) ? (u & 0x7fffffffu) : ~u;
    return __uint_as_float(b);
}

// Quantize 4 floats -> packed int8x4 (round-to-nearest, clamp +-127)
__device__ __forceinline__ uint32_t q4(float4 f, float inv) {
    int q0 = max(-127, min(127, __float2int_rn(f.x * inv)));
    int q1 = max(-127, min(127, __float2int_rn(f.y * inv)));
    int q2 = max(-127, min(127, __float2int_rn(f.z * inv)));
    int q3 = max(-127, min(127, __float2int_rn(f.w * inv)));
    return (uint32_t)(q0 & 0xff) | ((uint32_t)(q1 & 0xff) << 8) |
           ((uint32_t)(q2 & 0xff) << 16) | ((uint32_t)q3 << 24);
}

// ---------------------------------------------------------------------------
// Prep 1: per code row v (one warp): csq, sum|c|, max|c|   (validated R10)
// ---------------------------------------------------------------------------
__global__ void prep1_kernel(const float* __restrict__ cb) {
    int v = (blockIdx.x * blockDim.x + threadIdx.x) >> 5;
    int lane = threadIdx.x & 31;
    if (v >= VQ) return;
    const float4 x4 = *(const float4*)(cb + (size_t)v * DQ + lane * 4);
    float s = x4.x * x4.x + x4.y * x4.y + x4.z * x4.z + x4.w * x4.w;
    float ab = fabsf(x4.x) + fabsf(x4.y) + fabsf(x4.z) + fabsf(x4.w);
    float mx = fmaxf(fmaxf(fabsf(x4.x), fabsf(x4.y)),
                     fmaxf(fabsf(x4.z), fabsf(x4.w)));
#pragma unroll
    for (int off = 16; off; off >>= 1) {
        s += __shfl_down_sync(0xffffffffu, s, off);
        ab += __shfl_down_sync(0xffffffffu, ab, off);
        mx = fmaxf(mx, __shfl_down_sync(0xffffffffu, mx, off));
    }
    if (lane == 0) {
        g_csq[v] = s;
        g_cabrow[v] = ab;
        g_cmaxrow[v] = mx;
    }
}

// ---------------------------------------------------------------------------
// Prep 2: single block: reduce cmax/cab, quantize codebook to int8 (R10)
// ---------------------------------------------------------------------------
__global__ void prep2_kernel(const float* __restrict__ cb) {
    __shared__ float smax[1024], sab[1024];
    int tid = threadIdx.x;
    smax[tid] = g_cmaxrow[tid];
    sab[tid] = g_cabrow[tid];
    __syncthreads();
#pragma unroll
    for (int off = 512; off; off >>= 1) {
        if (tid < off) {
            smax[tid] = fmaxf(smax[tid], smax[tid + off]);
            sab[tid] = fmaxf(sab[tid], sab[tid + off]);
        }
        __syncthreads();
    }
    float cmax = fmaxf(smax[0], 1e-20f);
    if (tid == 0) {
        g_sc = cmax / 127.0f;
        g_cab = sab[0];
    }
    float inv = 127.0f / cmax;
    for (int i = tid; i < VQ * DQ; i += 1024) {
        int q = max(-127, min(127, __float2int_rn(cb[i] * inv)));
        g_ci8[i] = (signed char)q;
    }
}

// ---------------------------------------------------------------------------
// Main: int8 k32 IMMA screen (half the LDSM+MMA of the bf16 path) ->
// candidate queue (rigorous per-row margin) -> exact fp32 rescore ->
// codes + fused quantized gather. 512 threads, 16 warps (4x4), warp tile
// 32x32, CTA 128x128x128, 8 chunks, double-buffered int8 B.
// ---------------------------------------------------------------------------
__global__ void __launch_bounds__(NTHREADS, 1)
vq_kernel(const float* __restrict__ latents, const float* __restrict__ cb,
          float* __restrict__ codes, float* __restrict__ quant) {
    extern __shared__ unsigned char sm[];
    const uint32_t smb = smem_u32(sm);
    const int tid = threadIdx.x;
    const int lane = tid & 31;
    const int wid = tid >> 5;
    const int warp_m = wid & 3;    // 4 m-tiles of 32 rows
    const int warp_n = wid >> 2;   // 4 n-tiles of 32 cols
    const int b = blockIdx.y;
    const int t0 = blockIdx.x * TILE_M;

    unsigned long long* res = (unsigned long long*)(sm + OFF_RES);
    unsigned* rowmin = (unsigned*)(sm + OFF_ROWMIN);
    unsigned* qn = (unsigned*)(sm + OFF_QN);
    float* marg = (float*)(sm + OFF_MARG);   // SX accumulator during load
    unsigned* tmax = (unsigned*)(sm + OFF_TILEMAX);
    float* csq_s = (float*)(sm + OFF_CSQ);
    unsigned* queue = (unsigned*)(sm + OFF_QUEUE);
    float* Af = (float*)(sm + OFF_AF);

    const float scv = g_sc;
    const float cabv = g_cab;

    // Prefetch int8 B chunk 0
    {
        const signed char* src = g_ci8;
        for (int i = tid; i < 1024; i += NTHREADS) {
            int n = i >> 3, c = i & 7;
            CP_ASYNC16(smb + OFF_B + tswz8(n, c),
                       (const void*)(src + n * DQ + c * 16));
        }
        CP_COMMIT();
    }

    if (tid < TILE_M) {
        res[tid] = ~0ull;
        rowmin[tid] = 0xFFFFFFFFu;
        marg[tid] = 0.f;
    }
    if (tid == 0) { *qn = 0; *tmax = 0; }
    for (int i = tid; i < VQ; i += NTHREADS) csq_s[i] = g_csq[i];
    __syncthreads();

    // A pass 1: latents[b][d][t0+t] -> fp32 smem + per-row sum|x| + tile max
    // thread -> (t = tid&127, d in [ (tid>>7)*32, +32 )): coalesced over t.
    {
        const int t = tid & 127;
        const int d0 = (tid >> 7) * 32;
        const float* xg = latents + (size_t)b * DQ * TQ + t0 + t;
        float rsum = 0.f, lmax = 0.f;
#pragma unroll 8
        for (int j = 0; j < 32; j++) {
            int d = d0 + j;
            float x = xg[(size_t)d * TQ];
            Af[t * AF_STRIDE + d] = x;
            float ax = fabsf(x);
            rsum += ax;
            lmax = fmaxf(lmax, ax);
        }
        atomicAdd(&marg[t], rsum);   // one atomic per thread
#pragma unroll
        for (int off = 16; off; off >>= 1)
            lmax = fmaxf(lmax, __shfl_down_sync(0xffffffffu, lmax, off));
        if (lane == 0)
            atomicMax(tmax, __float_as_uint(lmax));  // nonneg: uint order ok
    }
    __syncthreads();

    const float tilemax = fmaxf(__uint_as_float(*tmax), 1e-20f);
    const float sx = tilemax / 127.0f;
    const float twoS = 2.0f * sx * scv;
    const float inv_sx = 127.0f / tilemax;

    // A pass 2: quantize Af -> int8 swizzled tile; finalize margins.
    {
        const int t = tid & 127;
        const int c0 = (tid >> 7) * 2;     // two 16B chunks per thread
#pragma unroll
        for (int cc = 0; cc < 2; cc++) {
            int c = c0 + cc;
            const float* rp = Af + t * AF_STRIDE + c * 16;
            uint32_t w0 = q4(*(const float4*)(rp + 0), inv_sx);
            uint32_t w1 = q4(*(const float4*)(rp + 4), inv_sx);
            uint32_t w2 = q4(*(const float4*)(rp + 8), inv_sx);
            uint32_t w3 = q4(*(const float4*)(rp + 12), inv_sx);
            uint4 w = make_uint4(w0, w1, w2, w3);
            *(uint4*)(sm + OFF_A8 + tswz8(t, c)) = w;
        }
    }
    if (tid < TILE_M)
        marg[tid] = (scv * marg[tid] + sx * cabv + 192.f * sx * scv) * 1.01f
                    + 0.02f;
    // (no sync needed here: the chunk-0 __syncthreads below covers A8/marg)

    // Per-thread ldmatrix constants (same addressing pattern as bf16 path;
    // validated for 128B int8 rows by R10's rel_err = 0.0)
    const int arow_in16 = lane & 15;
    const int kca = lane >> 4;
    const int brow_in16 = (lane & 7) | ((lane >> 4) << 3);
    const int kcb = (lane >> 3) & 1;

    int axr[2];
    uint32_t abase[2];
#pragma unroll
    for (int mi = 0; mi < 2; mi++) {
        int row = warp_m * 32 + mi * 16 + arow_in16;
        axr[mi] = row & 7;
        abase[mi] = (uint32_t)(row * 128);
    }
    int bxr[2];
    uint32_t bbase[2];
#pragma unroll
    for (int n4 = 0; n4 < 2; n4++) {
        int row = warp_n * 32 + n4 * 16 + brow_in16;
        bxr[n4] = row & 7;
        bbase[n4] = (uint32_t)(row * 128);
    }

    for (int vc = 0; vc < NCHUNK; vc++) {
        const int v0 = vc * TILE_N;
        const int buf = vc & 1;

        // Prefetch next chunk into the other buffer (R7 schedule)
        if (vc < NCHUNK - 1) {
            const signed char* src = g_ci8 + (size_t)(v0 + TILE_N) * DQ;
            uint32_t dbase = smb + OFF_B + (buf ^ 1) * BTILE;
            for (int i = tid; i < 1024; i += NTHREADS) {
                int n = i >> 3, c = i & 7;
                CP_ASYNC16(dbase + tswz8(n, c),
                           (const void*)(src + n * DQ + c * 16));
            }
            CP_COMMIT();
            CP_WAIT1();
        } else {
            CP_WAIT0();
        }
        __syncthreads();   // B[vc] visible; A8/marg ready (vc==0)

        int acc[2][4][4];
#pragma unroll
        for (int mi = 0; mi < 2; mi++)
#pragma unroll
            for (int ni = 0; ni < 4; ni++)
#pragma unroll
                for (int q = 0; q < 4; q++) acc[mi][ni][q] = 0;

        const uint32_t bsm = smb + OFF_B + buf * BTILE;
#pragma unroll
        for (int ks = 0; ks < 4; ks++) {
            uint32_t aF[2][4];
#pragma unroll
            for (int mi = 0; mi < 2; mi++) {
                uint32_t chunk = (uint32_t)(((ks << 1) | kca) ^ axr[mi]);
                LDMX4(aF[mi], smb + OFF_A8 + abase[mi] + (chunk << 4));
            }
            uint32_t bF[4][2];
#pragma unroll
            for (int n4 = 0; n4 < 2; n4++) {
                uint32_t chunk = (uint32_t)(((ks << 1) | kcb) ^ bxr[n4]);
                uint32_t r[4];
                LDMX4(r, bsm + bbase[n4] + (chunk << 4));
                bF[n4 * 2][0] = r[0]; bF[n4 * 2][1] = r[1];
                bF[n4 * 2 + 1][0] = r[2]; bF[n4 * 2 + 1][1] = r[3];
            }
#pragma unroll
            for (int mi = 0; mi < 2; mi++)
#pragma unroll
                for (int ni = 0; ni < 4; ni++)
                    mma_s8(acc[mi][ni], aF[mi], bF[ni]);
        }

        // Convert int acc -> fp32 scores IN PLACE (same 32 registers),
        // track per-thread row mins.
        float rm[4];
#pragma unroll
        for (int j = 0; j < 4; j++) rm[j] = 3.4e38f;
#pragma unroll
        for (int ni = 0; ni < 4; ni++) {
            int col0 = v0 + warp_n * 32 + ni * 8 + (lane & 3) * 2;
            float cs0 = csq_s[col0], cs1 = csq_s[col0 + 1];
#pragma unroll
            for (int mi = 0; mi < 2; mi++) {
                int* c = acc[mi][ni];
                float s0 = fmaf(-twoS, (float)c[0], cs0);
                float s1 = fmaf(-twoS, (float)c[1], cs1);
                float s2 = fmaf(-twoS, (float)c[2], cs0);
                float s3 = fmaf(-twoS, (float)c[3], cs1);
                c[0] = __float_as_int(s0);
                c[1] = __float_as_int(s1);
                c[2] = __float_as_int(s2);
                c[3] = __float_as_int(s3);
                float m01 = fminf(s0, s1), m23 = fminf(s2, s3);
                if (m01 < rm[mi * 2]) rm[mi * 2] = m01;
                if (m23 < rm[mi * 2 + 1]) rm[mi * 2 + 1] = m23;
            }
        }
        // rowmin monotone-decreasing: no barrier needed (stale read = safe
        // looser threshold; writer of true min reads its own update).
#pragma unroll
        for (int j = 0; j < 4; j++) {
            int row = warp_m * 32 + (j >> 1) * 16 + (j & 1) * 8 + (lane >> 2);
            atomicMin(&rowmin[row], fford(rm[j]));
        }

        // Insert candidates within per-row margin of running row min
#pragma unroll
        for (int mi = 0; mi < 2; mi++) {
            int rA = warp_m * 32 + mi * 16 + (lane >> 2);
            float thA = fford_inv(rowmin[rA]) + marg[rA];
            float thB = fford_inv(rowmin[rA + 8]) + marg[rA + 8];
#pragma unroll
            for (int ni = 0; ni < 4; ni++) {
                int col0 = v0 + warp_n * 32 + ni * 8 + (lane & 3) * 2;
                const int* c = acc[mi][ni];
                if (__int_as_float(c[0]) <= thA) {
                    unsigned k = atomicAdd(qn, 1u);
                    if (k < QCAP) queue[k] = ((unsigned)rA << 10) | col0;
                }
                if (__int_as_float(c[1]) <= thA) {
                    unsigned k = atomicAdd(qn, 1u);
                    if (k < QCAP) queue[k] = ((unsigned)rA << 10) | (col0 + 1);
                }
                if (__int_as_float(c[2]) <= thB) {
                    unsigned k = atomicAdd(qn, 1u);
                    if (k < QCAP) queue[k] = ((unsigned)(rA + 8) << 10) | col0;
                }
                if (__int_as_float(c[3]) <= thB) {
                    unsigned k = atomicAdd(qn, 1u);
                    if (k < QCAP)
                        queue[k] = ((unsigned)(rA + 8) << 10) | (col0 + 1);
                }
            }
        }
    }
    __syncthreads();

    // Exact fp32 rescore of candidates: one warp per queue entry
    {
        unsigned n = *qn;
        if (n > QCAP) n = QCAP;
        for (unsigned e = wid; e < n; e += 16) {
            unsigned ent = queue[e];
            int r = ent >> 10;
            int v = ent & 1023;
            const float4 xa = *(const float4*)(Af + r * AF_STRIDE + lane * 4);
            const float4 ca = *(const float4*)(cb + (size_t)v * DQ + lane * 4);
            float s = xa.x * ca.x + xa.y * ca.y + xa.z * ca.z + xa.w * ca.w;
#pragma unroll
            for (int off = 16; off; off >>= 1)
                s += __shfl_down_sync(0xffffffffu, s, off);
            if (lane == 0) {
                float score = fmaf(-2.f, s, csq_s[v]);
                unsigned long long pk =
                    ((unsigned long long)fford(score) << 32) | (unsigned)v;
                atomicMin(&res[r], pk);
            }
        }
    }
    __syncthreads();

    // Write codes (as float) and fused quantized gather
    if (tid < TILE_M)
        codes[(size_t)b * TQ + t0 + tid] = (float)(unsigned)(res[tid] & 1023u);

    {
        int t = tid & 127;
        int dh = tid >> 7;                 // 0..3: d-quarters
        int v = (int)(res[t] & 1023u);
        const float* crow = cb + (size_t)v * DQ + dh * 32;
        float* q = quant + (size_t)b * DQ * TQ + (size_t)(dh * 32) * TQ + t0 + t;
#pragma unroll
        for (int i = 0; i < 8; i++) {
            float4 c4 = *(const float4*)(crow + i * 4);
            q[(i * 4 + 0) * TQ] = c4.x;
            q[(i * 4 + 1) * TQ] = c4.y;
            q[(i * 4 + 2) * TQ] = c4.z;
            q[(i * 4 + 3) * TQ] = c4.w;
        }
    }
}

// ---------------------------------------------------------------------------
extern "C" void kernel_launch(void* const* d_in, const int* in_sizes, int n_in,
                              void* d_out, int out_size) {
    const float* latents = (const float*)d_in[0];   // (B, D, T) fp32
    const float* codebook = (const float*)d_in[1];  // (V, D)    fp32

    float* codes = (float*)d_out;             // B*T floats
    float* quant = (float*)d_out + BQ * TQ;   // B*D*T floats

    cudaFuncSetAttribute(vq_kernel,
                         cudaFuncAttributeMaxDynamicSharedMemorySize,
                         SMEM_TOTAL);

    prep1_kernel<<<(VQ * 32) / 256, 256>>>(codebook);
    prep2_kernel<<<1, 1024>>>(codebook);

    dim3 grid(TQ / TILE_M, BQ);   // (32, 16) = 512 blocks
    vq_kernel<<<grid, NTHREADS, SMEM_TOTAL>>>(latents, codebook, codes, quant);
}

// round 15
// speedup vs baseline: 1.2034x; 1.2034x over previous
#include <cuda_runtime.h>
#include <cuda_bf16.h>
#include <cstdint>

// Problem constants
#define BQ 16
#define DQ 128
#define TQ 4096
#define VQ 1024

#define TILE_M 64
#define TILE_N 128
#define NCHUNK 8
#define MARGIN 3.0f
#define QCAP 2048
#define NTHREADS 256

// Dynamic SMEM layout (bytes) -- total 62464: 3 CTAs/SM
#define OFF_RES    0          // 64 x u64 packed (score,idx)
#define OFF_ROWMIN 512        // 64 x u32
#define OFF_QN     768        // queue counter
#define OFF_CSQ    1024       // 1024 floats (4KB)
#define OFF_QUEUE  5120       // QCAP x u32 (8KB)
#define OFF_AH     13312      // bf16 A tile 16KB (swizzled)
#define OFF_B      29696      // bf16 B tile 32KB (single buffer)
#define SMEM_TOTAL 62464

__device__ float g_csq[VQ];
__device__ __nv_bfloat16 g_ch[VQ * DQ];

// ---------------------------------------------------------------------------
__device__ __forceinline__ uint32_t smem_u32(const void* p) {
    uint32_t a;
    asm("{ .reg .u64 t; cvta.to.shared.u64 t, %1; cvt.u32.u64 %0, t; }"
        : "=r"(a) : "l"(p));
    return a;
}

#define LDMX4(r, addr) \
    asm volatile("ldmatrix.sync.aligned.m8n8.x4.shared.b16 {%0,%1,%2,%3}, [%4];" \
        : "=r"((r)[0]), "=r"((r)[1]), "=r"((r)[2]), "=r"((r)[3]) \
        : "r"(addr))

__device__ __forceinline__ void mma_bf16(float* c, const uint32_t* a,
                                         const uint32_t* b) {
    asm volatile(
        "mma.sync.aligned.m16n8k16.row.col.f32.bf16.bf16.f32 "
        "{%0,%1,%2,%3}, {%4,%5,%6,%7}, {%8,%9}, {%0,%1,%2,%3};"
        : "+f"(c[0]), "+f"(c[1]), "+f"(c[2]), "+f"(c[3])
        : "r"(a[0]), "r"(a[1]), "r"(a[2]), "r"(a[3]), "r"(b[0]), "r"(b[1]));
}

#define CP_ASYNC16(dst, src) \
    asm volatile("cp.async.cg.shared.global [%0], [%1], 16;" \
        :: "r"(dst), "l"(src))
#define CP_COMMIT() asm volatile("cp.async.commit_group;" ::: "memory")
#define CP_WAIT0() asm volatile("cp.async.wait_group 0;" ::: "memory")

// Swizzled byte offset inside a (rows x 128) bf16 tile (256B rows, 16B chunks,
// chunk column XOR'd with row%8 -> conflict-free ldmatrix).
__device__ __forceinline__ uint32_t tswz(int row, int col2b) {
    return (uint32_t)(row * 256 + ((((col2b >> 3) ^ (row & 7)) << 4) |
                                   ((col2b & 7) * 2)));
}

// Order-preserving float <-> uint
__device__ __forceinline__ unsigned fford(float f) {
    unsigned u = __float_as_uint(f);
    return (u & 0x80000000u) ? ~u : (u | 0x80000000u);
}
__device__ __forceinline__ float fford_inv(unsigned u) {
    unsigned b = (u & 0x80000000u) ? (u & 0x7fffffffu) : ~u;
    return __uint_as_float(b);
}

// ---------------------------------------------------------------------------
// Prep: per code row v, csq[v] and bf16 conversion. One warp per row.
// ---------------------------------------------------------------------------
__global__ void prep_kernel(const float* __restrict__ cb) {
    int v = (blockIdx.x * blockDim.x + threadIdx.x) >> 5;
    int lane = threadIdx.x & 31;
    if (v >= VQ) return;
    const float4 x4 = *(const float4*)(cb + (size_t)v * DQ + lane * 4);
    float s = x4.x * x4.x + x4.y * x4.y + x4.z * x4.z + x4.w * x4.w;
#pragma unroll
    for (int off = 16; off; off >>= 1)
        s += __shfl_down_sync(0xffffffffu, s, off);
    if (lane == 0) g_csq[v] = s;
    __nv_bfloat162 p0 = __nv_bfloat162(__float2bfloat16(x4.x),
                                       __float2bfloat16(x4.y));
    __nv_bfloat162 p1 = __nv_bfloat162(__float2bfloat16(x4.z),
                                       __float2bfloat16(x4.w));
    *(__nv_bfloat162*)(g_ch + (size_t)v * DQ + lane * 4) = p0;
    *(__nv_bfloat162*)(g_ch + (size_t)v * DQ + lane * 4 + 2) = p1;
}

// ---------------------------------------------------------------------------
// Main: bf16 HMMA screen -> candidate queue -> exact fp32 rescore (latents
// read from gmem) -> codes + fused quantized gather.
// 256 threads, 8 warps (2x4), warp tile 32x32, CTA tile 64x128x128,
// V in 8 chunks, single-buffered B, 3 CTAs/SM (24 warps).
// ---------------------------------------------------------------------------
__global__ void __launch_bounds__(NTHREADS, 3)
vq_kernel(const float* __restrict__ latents, const float* __restrict__ cb,
          float* __restrict__ codes, float* __restrict__ quant) {
    extern __shared__ unsigned char sm[];
    const uint32_t smb = smem_u32(sm);
    const int tid = threadIdx.x;
    const int lane = tid & 31;
    const int wid = tid >> 5;
    const int warp_m = wid & 1;    // 2 m-tiles of 32 rows
    const int warp_n = wid >> 1;   // 4 n-tiles of 32 cols
    const int b = blockIdx.y;
    const int t0 = blockIdx.x * TILE_M;

    unsigned long long* res = (unsigned long long*)(sm + OFF_RES);
    unsigned* rowmin = (unsigned*)(sm + OFF_ROWMIN);
    unsigned* qn = (unsigned*)(sm + OFF_QN);
    float* csq_s = (float*)(sm + OFF_CSQ);
    unsigned* queue = (unsigned*)(sm + OFF_QUEUE);

    // Prefetch B chunk 0 immediately
    {
        const __nv_bfloat16* src = g_ch;
        for (int i = tid; i < 2048; i += NTHREADS) {
            int n = i >> 4, c = i & 15;
            CP_ASYNC16(smb + OFF_B + tswz(n, c * 8),
                       (const void*)(src + n * DQ + c * 8));
        }
        CP_COMMIT();
    }

    if (tid < TILE_M) {
        res[tid] = ~0ull;
        rowmin[tid] = 0xFFFFFFFFu;
    }
    if (tid == 0) *qn = 0;
    for (int i = tid; i < VQ; i += NTHREADS) csq_s[i] = g_csq[i];

    // A: latents[b][d][t0+t] -> bf16 swizzled tile
    {
        const float* xg = latents + (size_t)b * DQ * TQ + t0;
        for (int idx = tid; idx < DQ * TILE_M; idx += NTHREADS) {
            int d = idx >> 6;      // 0..127
            int t = idx & 63;      // coalesced over t
            float x = xg[(size_t)d * TQ + t];
            *(__nv_bfloat16*)(sm + OFF_AH + tswz(t, d)) = __float2bfloat16(x);
        }
    }

    // Per-thread ldmatrix constants (validated R5-R13)
    const int arow_in16 = lane & 15;
    const int kca = lane >> 4;
    const int brow_in16 = (lane & 7) | ((lane >> 4) << 3);
    const int kcb = (lane >> 3) & 1;

    int axr[2];
    uint32_t abase[2];
#pragma unroll
    for (int mi = 0; mi < 2; mi++) {
        int row = warp_m * 32 + mi * 16 + arow_in16;
        axr[mi] = row & 7;
        abase[mi] = (uint32_t)(row * 256);
    }
    int bxr[2];
    uint32_t bbase[2];
#pragma unroll
    for (int n4 = 0; n4 < 2; n4++) {
        int row = warp_n * 32 + n4 * 16 + brow_in16;
        bxr[n4] = row & 7;
        bbase[n4] = (uint32_t)(row * 256);
    }

    for (int vc = 0; vc < NCHUNK; vc++) {
        const int v0 = vc * TILE_N;

        CP_WAIT0();
        __syncthreads();   // B[vc] visible; A tile ready (vc==0)

        float acc[2][4][4];
#pragma unroll
        for (int mi = 0; mi < 2; mi++)
#pragma unroll
            for (int ni = 0; ni < 4; ni++)
#pragma unroll
                for (int q = 0; q < 4; q++) acc[mi][ni][q] = 0.f;

#pragma unroll
        for (int ks = 0; ks < 8; ks++) {
            uint32_t aH[2][4];
#pragma unroll
            for (int mi = 0; mi < 2; mi++) {
                uint32_t co = (uint32_t)((((ks << 1) | kca) ^ axr[mi]) << 4);
                LDMX4(aH[mi], smb + OFF_AH + abase[mi] + co);
            }
            uint32_t bH[4][2];
#pragma unroll
            for (int n4 = 0; n4 < 2; n4++) {
                uint32_t co = (uint32_t)((((ks << 1) | kcb) ^ bxr[n4]) << 4);
                uint32_t r[4];
                LDMX4(r, smb + OFF_B + bbase[n4] + co);
                bH[n4 * 2][0] = r[0]; bH[n4 * 2][1] = r[1];
                bH[n4 * 2 + 1][0] = r[2]; bH[n4 * 2 + 1][1] = r[3];
            }
#pragma unroll
            for (int mi = 0; mi < 2; mi++)
#pragma unroll
                for (int ni = 0; ni < 4; ni++)
                    mma_bf16(acc[mi][ni], aH[mi], bH[ni]);
        }

        // Convert acc -> cheap scores in place, track per-thread row mins
        float rm[4];
#pragma unroll
        for (int j = 0; j < 4; j++) rm[j] = 3.4e38f;
#pragma unroll
        for (int ni = 0; ni < 4; ni++) {
            int col0 = v0 + warp_n * 32 + ni * 8 + (lane & 3) * 2;
            float cs0 = csq_s[col0], cs1 = csq_s[col0 + 1];
#pragma unroll
            for (int mi = 0; mi < 2; mi++) {
                float* c = acc[mi][ni];
                c[0] = fmaf(-2.f, c[0], cs0);
                c[1] = fmaf(-2.f, c[1], cs1);
                c[2] = fmaf(-2.f, c[2], cs0);
                c[3] = fmaf(-2.f, c[3], cs1);
                float m01 = fminf(c[0], c[1]), m23 = fminf(c[2], c[3]);
                if (m01 < rm[mi * 2]) rm[mi * 2] = m01;
                if (m23 < rm[mi * 2 + 1]) rm[mi * 2 + 1] = m23;
            }
        }
#pragma unroll
        for (int j = 0; j < 4; j++) {
            int row = warp_m * 32 + (j >> 1) * 16 + (j & 1) * 8 + (lane >> 2);
            atomicMin(&rowmin[row], fford(rm[j]));
        }
        __syncthreads();   // rowmin complete; all B ldmatrix reads retired

        // Issue next chunk's B load (single buffer; overlaps with insert
        // phase and the other two resident CTAs' compute)
        if (vc < NCHUNK - 1) {
            const __nv_bfloat16* src = g_ch + (size_t)(v0 + TILE_N) * DQ;
            for (int i = tid; i < 2048; i += NTHREADS) {
                int n = i >> 4, c = i & 15;
                CP_ASYNC16(smb + OFF_B + tswz(n, c * 8),
                           (const void*)(src + n * DQ + c * 8));
            }
            CP_COMMIT();
        }

        // Insert candidates within MARGIN of running row min
#pragma unroll
        for (int mi = 0; mi < 2; mi++) {
            int rA = warp_m * 32 + mi * 16 + (lane >> 2);
            float thA = fford_inv(rowmin[rA]) + MARGIN;
            float thB = fford_inv(rowmin[rA + 8]) + MARGIN;
#pragma unroll
            for (int ni = 0; ni < 4; ni++) {
                int col0 = v0 + warp_n * 32 + ni * 8 + (lane & 3) * 2;
                const float* c = acc[mi][ni];
                if (c[0] <= thA) {
                    unsigned k = atomicAdd(qn, 1u);
                    if (k < QCAP) queue[k] = ((unsigned)rA << 10) | col0;
                }
                if (c[1] <= thA) {
                    unsigned k = atomicAdd(qn, 1u);
                    if (k < QCAP) queue[k] = ((unsigned)rA << 10) | (col0 + 1);
                }
                if (c[2] <= thB) {
                    unsigned k = atomicAdd(qn, 1u);
                    if (k < QCAP) queue[k] = ((unsigned)(rA + 8) << 10) | col0;
                }
                if (c[3] <= thB) {
                    unsigned k = atomicAdd(qn, 1u);
                    if (k < QCAP)
                        queue[k] = ((unsigned)(rA + 8) << 10) | (col0 + 1);
                }
            }
        }
    }
    __syncthreads();

    // Exact fp32 rescore: one warp per queue entry; latents read from gmem
    // (L2-resident; lane covers 4 d-values, stride TQ between d).
    {
        const float* xg = latents + (size_t)b * DQ * TQ + t0;
        unsigned n = *qn;
        if (n > QCAP) n = QCAP;
        for (unsigned e = wid; e < n; e += 8) {
            unsigned ent = queue[e];
            int r = ent >> 10;
            int v = ent & 1023;
            const float* xr = xg + r;
            const float4 ca = *(const float4*)(cb + (size_t)v * DQ + lane * 4);
            float x0 = xr[(size_t)(lane * 4 + 0) * TQ];
            float x1 = xr[(size_t)(lane * 4 + 1) * TQ];
            float x2 = xr[(size_t)(lane * 4 + 2) * TQ];
            float x3 = xr[(size_t)(lane * 4 + 3) * TQ];
            float s = x0 * ca.x + x1 * ca.y + x2 * ca.z + x3 * ca.w;
#pragma unroll
            for (int off = 16; off; off >>= 1)
                s += __shfl_down_sync(0xffffffffu, s, off);
            if (lane == 0) {
                float score = fmaf(-2.f, s, csq_s[v]);
                unsigned long long pk =
                    ((unsigned long long)fford(score) << 32) | (unsigned)v;
                atomicMin(&res[r], pk);
            }
        }
    }
    __syncthreads();

    // Write codes (as float) and fused quantized gather
    if (tid < TILE_M)
        codes[(size_t)b * TQ + t0 + tid] = (float)(unsigned)(res[tid] & 1023u);

    {
        int t = tid & 63;
        int dh = tid >> 6;                 // 0..3: d-quarters
        int v = (int)(res[t] & 1023u);
        const float* crow = cb + (size_t)v * DQ + dh * 32;
        float* q = quant + (size_t)b * DQ * TQ + (size_t)(dh * 32) * TQ + t0 + t;
#pragma unroll
        for (int i = 0; i < 8; i++) {
            float4 c4 = *(const float4*)(crow + i * 4);
            q[(i * 4 + 0) * TQ] = c4.x;
            q[(i * 4 + 1) * TQ] = c4.y;
            q[(i * 4 + 2) * TQ] = c4.z;
            q[(i * 4 + 3) * TQ] = c4.w;
        }
    }
}

// ---------------------------------------------------------------------------
extern "C" void kernel_launch(void* const* d_in, const int* in_sizes, int n_in,
                              void* d_out, int out_size) {
    const float* latents = (const float*)d_in[0];   // (B, D, T) fp32
    const float* codebook = (const float*)d_in[1];  // (V, D)    fp32

    float* codes = (float*)d_out;             // B*T floats
    float* quant = (float*)d_out + BQ * TQ;   // B*D*T floats

    cudaFuncSetAttribute(vq_kernel,
                         cudaFuncAttributeMaxDynamicSharedMemorySize,
                         SMEM_TOTAL);

    prep_kernel<<<(VQ * 32) / 256, 256>>>(codebook);

    dim3 grid(TQ / TILE_M, BQ);   // (64, 16) = 1024 blocks
    vq_kernel<<<grid, NTHREADS, SMEM_TOTAL>>>(latents, codebook, codes, quant);
}

// round 16
// speedup vs baseline: 1.8936x; 1.5735x over previous
#include <cuda_runtime.h>
#include <cuda_bf16.h>
#include <cstdint>

// Problem constants
#define BQ 16
#define DQ 128
#define TQ 4096
#define VQ 1024

#define TILE_M 128
#define TILE_N 128
#define NCHUNK 8
#define MARGIN 3.0f
#define QCAP 4096
#define NTHREADS 1024

// Dynamic SMEM layout (bytes) -- 188416 total, 1 CTA/SM, 32 warps
#define OFF_RES    0          // 128 x u64 packed (score,idx)
#define OFF_ROWMIN 1024       // 128 x u32
#define OFF_QN     1536       // queue counter
#define OFF_CSQ    2048       // 1024 floats
#define OFF_QUEUE  6144       // QCAP x u32 (16KB)
#define OFF_AF     22528      // fp32 A [128][AF_STRIDE]
#define AF_STRIDE  132
#define OFF_AH     90112      // bf16 A tile 32KB (swizzled)
#define OFF_B      122880     // bf16 B tiles, 2 x 32KB (double buffer)
#define BTILE      32768
#define SMEM_TOTAL 188416

__device__ float g_csq[VQ];
__device__ __nv_bfloat16 g_ch[VQ * DQ];

// ---------------------------------------------------------------------------
__device__ __forceinline__ uint32_t smem_u32(const void* p) {
    uint32_t a;
    asm("{ .reg .u64 t; cvta.to.shared.u64 t, %1; cvt.u32.u64 %0, t; }"
        : "=r"(a) : "l"(p));
    return a;
}

#define LDMX4(r, addr) \
    asm volatile("ldmatrix.sync.aligned.m8n8.x4.shared.b16 {%0,%1,%2,%3}, [%4];" \
        : "=r"((r)[0]), "=r"((r)[1]), "=r"((r)[2]), "=r"((r)[3]) \
        : "r"(addr))

__device__ __forceinline__ void mma_bf16(float* c, const uint32_t* a,
                                         const uint32_t* b) {
    asm volatile(
        "mma.sync.aligned.m16n8k16.row.col.f32.bf16.bf16.f32 "
        "{%0,%1,%2,%3}, {%4,%5,%6,%7}, {%8,%9}, {%0,%1,%2,%3};"
        : "+f"(c[0]), "+f"(c[1]), "+f"(c[2]), "+f"(c[3])
        : "r"(a[0]), "r"(a[1]), "r"(a[2]), "r"(a[3]), "r"(b[0]), "r"(b[1]));
}

#define CP_ASYNC16(dst, src) \
    asm volatile("cp.async.cg.shared.global [%0], [%1], 16;" \
        :: "r"(dst), "l"(src))
#define CP_COMMIT() asm volatile("cp.async.commit_group;" ::: "memory")
#define CP_WAIT1() asm volatile("cp.async.wait_group 1;" ::: "memory")
#define CP_WAIT0() asm volatile("cp.async.wait_group 0;" ::: "memory")

// Swizzled byte offset inside a (rows x 128) bf16 tile (256B rows, 16B chunks,
// chunk column XOR'd with row%8 -> conflict-free ldmatrix).
__device__ __forceinline__ uint32_t tswz(int row, int col2b) {
    return (uint32_t)(row * 256 + ((((col2b >> 3) ^ (row & 7)) << 4) |
                                   ((col2b & 7) * 2)));
}

// Order-preserving float <-> uint
__device__ __forceinline__ unsigned fford(float f) {
    unsigned u = __float_as_uint(f);
    return (u & 0x80000000u) ? ~u : (u | 0x80000000u);
}
__device__ __forceinline__ float fford_inv(unsigned u) {
    unsigned b = (u & 0x80000000u) ? (u & 0x7fffffffu) : ~u;
    return __uint_as_float(b);
}

// ---------------------------------------------------------------------------
// Prep: per code row v, csq[v] and bf16 conversion. One warp per row.
// ---------------------------------------------------------------------------
__global__ void prep_kernel(const float* __restrict__ cb) {
    int v = (blockIdx.x * blockDim.x + threadIdx.x) >> 5;
    int lane = threadIdx.x & 31;
    if (v >= VQ) return;
    const float4 x4 = *(const float4*)(cb + (size_t)v * DQ + lane * 4);
    float s = x4.x * x4.x + x4.y * x4.y + x4.z * x4.z + x4.w * x4.w;
#pragma unroll
    for (int off = 16; off; off >>= 1)
        s += __shfl_down_sync(0xffffffffu, s, off);
    if (lane == 0) g_csq[v] = s;
    __nv_bfloat162 p0 = __nv_bfloat162(__float2bfloat16(x4.x),
                                       __float2bfloat16(x4.y));
    __nv_bfloat162 p1 = __nv_bfloat162(__float2bfloat16(x4.z),
                                       __float2bfloat16(x4.w));
    *(__nv_bfloat162*)(g_ch + (size_t)v * DQ + lane * 4) = p0;
    *(__nv_bfloat162*)(g_ch + (size_t)v * DQ + lane * 4 + 2) = p1;
}

// ---------------------------------------------------------------------------
// Main: bf16 HMMA screen -> candidate queue -> exact fp32 rescore ->
// codes + fused quantized gather.  1024 threads, 32 warps (8x4), warp tile
// 16x32, CTA tile 128x128x128, V in 8 chunks, double-buffered B.
// 2x the warp parallelism of the R7-R13 plateau kernels at identical
// algorithm + B traffic.
// ---------------------------------------------------------------------------
__global__ void __launch_bounds__(NTHREADS, 1)
vq_kernel(const float* __restrict__ latents, const float* __restrict__ cb,
          float* __restrict__ codes, float* __restrict__ quant) {
    extern __shared__ unsigned char sm[];
    const uint32_t smb = smem_u32(sm);
    const int tid = threadIdx.x;
    const int lane = tid & 31;
    const int wid = tid >> 5;
    const int warp_m = wid & 7;    // 8 m-tiles of 16 rows
    const int warp_n = wid >> 3;   // 4 n-tiles of 32 cols
    const int b = blockIdx.y;
    const int t0 = blockIdx.x * TILE_M;

    unsigned long long* res = (unsigned long long*)(sm + OFF_RES);
    unsigned* rowmin = (unsigned*)(sm + OFF_ROWMIN);
    unsigned* qn = (unsigned*)(sm + OFF_QN);
    float* csq_s = (float*)(sm + OFF_CSQ);
    float* Af = (float*)(sm + OFF_AF);
    unsigned* queue = (unsigned*)(sm + OFF_QUEUE);

    // Prefetch B chunk 0
    {
        const __nv_bfloat16* src = g_ch;
        for (int i = tid; i < 2048; i += NTHREADS) {
            int n = i >> 4, c = i & 15;
            CP_ASYNC16(smb + OFF_B + tswz(n, c * 8),
                       (const void*)(src + n * DQ + c * 8));
        }
        CP_COMMIT();
    }

    if (tid < TILE_M) {
        res[tid] = ~0ull;
        rowmin[tid] = 0xFFFFFFFFu;
    }
    if (tid == 0) *qn = 0;
    if (tid < VQ) csq_s[tid] = g_csq[tid];

    // A: latents[b][d][t0+t] -> bf16 swizzled tile + fp32 copy
    {
        const float* xg = latents + (size_t)b * DQ * TQ + t0;
        for (int idx = tid; idx < DQ * TILE_M; idx += NTHREADS) {
            int d = idx >> 7;
            int t = idx & 127;     // coalesced over t
            float x = xg[(size_t)d * TQ + t];
            *(__nv_bfloat16*)(sm + OFF_AH + tswz(t, d)) = __float2bfloat16(x);
            Af[t * AF_STRIDE + d] = x;
        }
    }

    // Per-thread ldmatrix constants (addressing validated R5-R13)
    const int arow_in16 = lane & 15;
    const int kca = lane >> 4;
    const int brow_in16 = (lane & 7) | ((lane >> 4) << 3);
    const int kcb = (lane >> 3) & 1;

    const int arow = warp_m * 16 + arow_in16;
    const int axr = arow & 7;
    const uint32_t abase = (uint32_t)(arow * 256);

    int bxr[2];
    uint32_t bbase[2];
#pragma unroll
    for (int n4 = 0; n4 < 2; n4++) {
        int row = warp_n * 32 + n4 * 16 + brow_in16;
        bxr[n4] = row & 7;
        bbase[n4] = (uint32_t)(row * 256);
    }

    for (int vc = 0; vc < NCHUNK; vc++) {
        const int v0 = vc * TILE_N;
        const int buf = vc & 1;

        // Prefetch next chunk into the other buffer (R7 schedule)
        if (vc < NCHUNK - 1) {
            const __nv_bfloat16* src = g_ch + (size_t)(v0 + TILE_N) * DQ;
            uint32_t dbase = smb + OFF_B + (buf ^ 1) * BTILE;
            for (int i = tid; i < 2048; i += NTHREADS) {
                int n = i >> 4, c = i & 15;
                CP_ASYNC16(dbase + tswz(n, c * 8),
                           (const void*)(src + n * DQ + c * 8));
            }
            CP_COMMIT();
            CP_WAIT1();
        } else {
            CP_WAIT0();
        }
        __syncthreads();   // B[vc] visible; A tile ready (vc==0)

        float acc[4][4];
#pragma unroll
        for (int ni = 0; ni < 4; ni++)
#pragma unroll
            for (int q = 0; q < 4; q++) acc[ni][q] = 0.f;

        const uint32_t bsm = smb + OFF_B + buf * BTILE;
#pragma unroll
        for (int ks = 0; ks < 8; ks++) {
            uint32_t aH[4];
            {
                uint32_t co = (uint32_t)((((ks << 1) | kca) ^ axr) << 4);
                LDMX4(aH, smb + OFF_AH + abase + co);
            }
            uint32_t bH[4][2];
#pragma unroll
            for (int n4 = 0; n4 < 2; n4++) {
                uint32_t co = (uint32_t)((((ks << 1) | kcb) ^ bxr[n4]) << 4);
                uint32_t r[4];
                LDMX4(r, bsm + bbase[n4] + co);
                bH[n4 * 2][0] = r[0]; bH[n4 * 2][1] = r[1];
                bH[n4 * 2 + 1][0] = r[2]; bH[n4 * 2 + 1][1] = r[3];
            }
#pragma unroll
            for (int ni = 0; ni < 4; ni++)
                mma_bf16(acc[ni], aH, bH[ni]);
        }

        // Convert acc -> cheap scores in place, track per-thread row mins
        float rm0 = 3.4e38f, rm1 = 3.4e38f;
#pragma unroll
        for (int ni = 0; ni < 4; ni++) {
            int col0 = v0 + warp_n * 32 + ni * 8 + (lane & 3) * 2;
            float cs0 = csq_s[col0], cs1 = csq_s[col0 + 1];
            float* c = acc[ni];
            c[0] = fmaf(-2.f, c[0], cs0);
            c[1] = fmaf(-2.f, c[1], cs1);
            c[2] = fmaf(-2.f, c[2], cs0);
            c[3] = fmaf(-2.f, c[3], cs1);
            rm0 = fminf(rm0, fminf(c[0], c[1]));
            rm1 = fminf(rm1, fminf(c[2], c[3]));
        }
        // rowmin monotone-decreasing: no barrier needed (stale read = safe
        // looser threshold; writer of true min reads its own update).
        {
            int row = warp_m * 16 + (lane >> 2);
            atomicMin(&rowmin[row], fford(rm0));
            atomicMin(&rowmin[row + 8], fford(rm1));
        }

        // Insert candidates within MARGIN of running row min
        {
            int rA = warp_m * 16 + (lane >> 2);
            float thA = fford_inv(rowmin[rA]) + MARGIN;
            float thB = fford_inv(rowmin[rA + 8]) + MARGIN;
#pragma unroll
            for (int ni = 0; ni < 4; ni++) {
                int col0 = v0 + warp_n * 32 + ni * 8 + (lane & 3) * 2;
                const float* c = acc[ni];
                if (c[0] <= thA) {
                    unsigned k = atomicAdd(qn, 1u);
                    if (k < QCAP) queue[k] = ((unsigned)rA << 10) | col0;
                }
                if (c[1] <= thA) {
                    unsigned k = atomicAdd(qn, 1u);
                    if (k < QCAP) queue[k] = ((unsigned)rA << 10) | (col0 + 1);
                }
                if (c[2] <= thB) {
                    unsigned k = atomicAdd(qn, 1u);
                    if (k < QCAP) queue[k] = ((unsigned)(rA + 8) << 10) | col0;
                }
                if (c[3] <= thB) {
                    unsigned k = atomicAdd(qn, 1u);
                    if (k < QCAP)
                        queue[k] = ((unsigned)(rA + 8) << 10) | (col0 + 1);
                }
            }
        }
    }
    __syncthreads();

    // Exact fp32 rescore of candidates: one warp per queue entry
    {
        unsigned n = *qn;
        if (n > QCAP) n = QCAP;
        for (unsigned e = wid; e < n; e += 32) {
            unsigned ent = queue[e];
            int r = ent >> 10;
            int v = ent & 1023;
            const float4 xa = *(const float4*)(Af + r * AF_STRIDE + lane * 4);
            const float4 ca = *(const float4*)(cb + (size_t)v * DQ + lane * 4);
            float s = xa.x * ca.x + xa.y * ca.y + xa.z * ca.z + xa.w * ca.w;
#pragma unroll
            for (int off = 16; off; off >>= 1)
                s += __shfl_down_sync(0xffffffffu, s, off);
            if (lane == 0) {
                float score = fmaf(-2.f, s, csq_s[v]);
                unsigned long long pk =
                    ((unsigned long long)fford(score) << 32) | (unsigned)v;
                atomicMin(&res[r], pk);
            }
        }
    }
    __syncthreads();

    // Write codes (as float) and fused quantized gather
    if (tid < TILE_M)
        codes[(size_t)b * TQ + t0 + tid] = (float)(unsigned)(res[tid] & 1023u);

    {
        int t = tid & 127;
        int dh = tid >> 7;                 // 0..7: d-eighths (16 each)
        int v = (int)(res[t] & 1023u);
        const float* crow = cb + (size_t)v * DQ + dh * 16;
        float* q = quant + (size_t)b * DQ * TQ + (size_t)(dh * 16) * TQ + t0 + t;
#pragma unroll
        for (int i = 0; i < 4; i++) {
            float4 c4 = *(const float4*)(crow + i * 4);
            q[(i * 4 + 0) * TQ] = c4.x;
            q[(i * 4 + 1) * TQ] = c4.y;
            q[(i * 4 + 2) * TQ] = c4.z;
            q[(i * 4 + 3) * TQ] = c4.w;
        }
    }
}

// ---------------------------------------------------------------------------
extern "C" void kernel_launch(void* const* d_in, const int* in_sizes, int n_in,
                              void* d_out, int out_size) {
    const float* latents = (const float*)d_in[0];   // (B, D, T) fp32
    const float* codebook = (const float*)d_in[1];  // (V, D)    fp32

    float* codes = (float*)d_out;             // B*T floats
    float* quant = (float*)d_out + BQ * TQ;   // B*D*T floats

    cudaFuncSetAttribute(vq_kernel,
                         cudaFuncAttributeMaxDynamicSharedMemorySize,
                         SMEM_TOTAL);

    prep_kernel<<<(VQ * 32) / 256, 256>>>(codebook);

    dim3 grid(TQ / TILE_M, BQ);   // (32, 16) = 512 blocks
    vq_kernel<<<grid, NTHREADS, SMEM_TOTAL>>>(latents, codebook, codes, quant);
}

// round 17
// speedup vs baseline: 1.9412x; 1.0251x over previous
#include <cuda_runtime.h>
#include <cuda_bf16.h>
#include <cstdint>

// Problem constants
#define BQ 16
#define DQ 128
#define TQ 4096
#define VQ 1024

#define TILE_M 128
#define TILE_N 128
#define NCHUNK 8
#define MARGIN 3.0f
#define QCAP 4096
#define NTHREADS 1024

// Dynamic SMEM layout (bytes) -- 188416 total, 1 CTA/SM, 32 warps
#define OFF_RES    0          // 128 x u64 packed (score,idx)
#define OFF_ROWMIN 1024       // 128 x u32
#define OFF_QN     1536       // queue counter
#define OFF_MBAR   1552       // 2 x u64 mbarriers
#define OFF_CSQ    2048       // 1024 floats
#define OFF_QUEUE  6144       // QCAP x u32 (16KB)
#define OFF_AF     22528      // fp32 A [128][AF_STRIDE]
#define AF_STRIDE  132
#define OFF_AH     90112      // bf16 A tile 32KB (swizzled)
#define OFF_B      122880     // bf16 B tiles, 2 x 32KB (double buffer)
#define BTILE      32768
#define SMEM_TOTAL 188416

__device__ float g_csq[VQ];
// Codebook bf16, pre-swizzled chunk-tile layout: 8 chunks x 32KB, each chunk
// byte-identical to the smem B tile -> per-chunk load is ONE bulk copy.
__device__ __align__(16) unsigned char g_chsw[VQ * DQ * 2];

// ---------------------------------------------------------------------------
__device__ __forceinline__ uint32_t smem_u32(const void* p) {
    uint32_t a;
    asm("{ .reg .u64 t; cvta.to.shared.u64 t, %1; cvt.u32.u64 %0, t; }"
        : "=r"(a) : "l"(p));
    return a;
}

#define LDMX4(r, addr) \
    asm volatile("ldmatrix.sync.aligned.m8n8.x4.shared.b16 {%0,%1,%2,%3}, [%4];" \
        : "=r"((r)[0]), "=r"((r)[1]), "=r"((r)[2]), "=r"((r)[3]) \
        : "r"(addr))

__device__ __forceinline__ void mma_bf16(float* c, const uint32_t* a,
                                         const uint32_t* b) {
    asm volatile(
        "mma.sync.aligned.m16n8k16.row.col.f32.bf16.bf16.f32 "
        "{%0,%1,%2,%3}, {%4,%5,%6,%7}, {%8,%9}, {%0,%1,%2,%3};"
        : "+f"(c[0]), "+f"(c[1]), "+f"(c[2]), "+f"(c[3])
        : "r"(a[0]), "r"(a[1]), "r"(a[2]), "r"(a[3]), "r"(b[0]), "r"(b[1]));
}

#define MBARRIER_INIT(mbar, count) \
    asm volatile("mbarrier.init.shared.b64 [%0], %1;" \
        :: "r"((uint32_t)(mbar)), "r"((uint32_t)(count)) : "memory")
#define MBARRIER_EXPECT_TX(mbar, bytes) \
    asm volatile("mbarrier.arrive.expect_tx.shared.b64 _, [%0], %1;" \
        :: "r"((uint32_t)(mbar)), "r"((uint32_t)(bytes)) : "memory")
#define FENCE_PROXY_ASYNC() \
    asm volatile("fence.proxy.async.shared::cta;" ::: "memory")
#define BULK_LOAD(dst, src, bytes, mbar) \
    asm volatile( \
        "cp.async.bulk.shared::cluster.global.mbarrier::complete_tx::bytes " \
        "[%0], [%1], %2, [%3];" \
        :: "r"((uint32_t)(dst)), "l"(src), "r"((uint32_t)(bytes)), \
           "r"((uint32_t)(mbar)) : "memory")

#define MBARRIER_WAIT_PARITY(mbar_addr, phase_parity) do { \
    uint32_t _mbar = (uint32_t)(mbar_addr); \
    uint32_t _parity = (uint32_t)(phase_parity); \
    uint32_t _done; \
    asm volatile( \
        "{\n\t.reg .pred p;\n\t" \
        "mbarrier.try_wait.parity.acquire.cta.shared::cta.b64 p, [%1], %2;\n\t" \
        "selp.b32 %0, 1, 0, p;\n\t}" \
        : "=r"(_done) : "r"(_mbar), "r"(_parity) : "memory"); \
    if (!_done) { \
        asm volatile( \
            "{\n\t.reg .pred P1;\n\t" \
            "WAIT_LOOP_%=:\n\t" \
            "mbarrier.try_wait.parity.acquire.cta.shared::cta.b64 P1, [%0], %1, 0x989680;\n\t" \
            "@P1 bra.uni WAIT_DONE_%=;\n\t" \
            "bra.uni WAIT_LOOP_%=;\n\t" \
            "WAIT_DONE_%=:\n\t}" \
            :: "r"(_mbar), "r"(_parity) : "memory"); \
    } \
} while (0)

// Swizzled byte offset inside a (rows x 128) bf16 tile (256B rows, 16B chunks,
// chunk column XOR'd with row%8 -> conflict-free ldmatrix).
__device__ __forceinline__ uint32_t tswz(int row, int col2b) {
    return (uint32_t)(row * 256 + ((((col2b >> 3) ^ (row & 7)) << 4) |
                                   ((col2b & 7) * 2)));
}

// Order-preserving float <-> uint
__device__ __forceinline__ unsigned fford(float f) {
    unsigned u = __float_as_uint(f);
    return (u & 0x80000000u) ? ~u : (u | 0x80000000u);
}
__device__ __forceinline__ float fford_inv(unsigned u) {
    unsigned b = (u & 0x80000000u) ? (u & 0x7fffffffu) : ~u;
    return __uint_as_float(b);
}

// ---------------------------------------------------------------------------
// Prep: per code row v (one warp): csq[v]; bf16 codebook written directly in
// the pre-swizzled chunk-tile layout.
// ---------------------------------------------------------------------------
__global__ void prep_kernel(const float* __restrict__ cb) {
    int v = (blockIdx.x * blockDim.x + threadIdx.x) >> 5;
    int lane = threadIdx.x & 31;
    if (v >= VQ) return;
    const float4 x4 = *(const float4*)(cb + (size_t)v * DQ + lane * 4);
    float s = x4.x * x4.x + x4.y * x4.y + x4.z * x4.z + x4.w * x4.w;
#pragma unroll
    for (int off = 16; off; off >>= 1)
        s += __shfl_down_sync(0xffffffffu, s, off);
    if (lane == 0) g_csq[v] = s;

    __nv_bfloat162 p0 = __nv_bfloat162(__float2bfloat16(x4.x),
                                       __float2bfloat16(x4.y));
    __nv_bfloat162 p1 = __nv_bfloat162(__float2bfloat16(x4.z),
                                       __float2bfloat16(x4.w));
    // Destination: chunk (v>>7), row n = v&127, bf16 col = lane*4 (8 bytes,
    // 8B-aligned inside the swizzled tile).
    int n = v & 127;
    uint32_t off8 = (uint32_t)(v >> 7) * (uint32_t)BTILE + tswz(n, lane * 4);
    uint2 w;
    w.x = *(const unsigned*)&p0;
    w.y = *(const unsigned*)&p1;
    *(uint2*)(g_chsw + off8) = w;
}

// ---------------------------------------------------------------------------
// Main: bf16 HMMA screen -> candidate queue -> exact fp32 rescore ->
// codes + fused quantized gather.  1024 threads, 32 warps (8x4), warp tile
// 16x32, CTA tile 128x128x128, V in 8 chunks.  B loaded per chunk with ONE
// cp.async.bulk (replaces 2048 LDGSTS -> kills the 8cyc/op issue floor).
// ---------------------------------------------------------------------------
__global__ void __launch_bounds__(NTHREADS, 1)
vq_kernel(const float* __restrict__ latents, const float* __restrict__ cb,
          float* __restrict__ codes, float* __restrict__ quant) {
    extern __shared__ unsigned char sm[];
    const uint32_t smb = smem_u32(sm);
    const int tid = threadIdx.x;
    const int lane = tid & 31;
    const int wid = tid >> 5;
    const int warp_m = wid & 7;    // 8 m-tiles of 16 rows
    const int warp_n = wid >> 3;   // 4 n-tiles of 32 cols
    const int b = blockIdx.y;
    const int t0 = blockIdx.x * TILE_M;

    unsigned long long* res = (unsigned long long*)(sm + OFF_RES);
    unsigned* rowmin = (unsigned*)(sm + OFF_ROWMIN);
    unsigned* qn = (unsigned*)(sm + OFF_QN);
    float* csq_s = (float*)(sm + OFF_CSQ);
    float* Af = (float*)(sm + OFF_AF);
    unsigned* queue = (unsigned*)(sm + OFF_QUEUE);

    // Init mbarriers + issue bulk load of chunk 0 (single thread)
    if (tid == 0) {
        MBARRIER_INIT(smb + OFF_MBAR, 1);
        MBARRIER_INIT(smb + OFF_MBAR + 8, 1);
        FENCE_PROXY_ASYNC();
        MBARRIER_EXPECT_TX(smb + OFF_MBAR, BTILE);
        BULK_LOAD(smb + OFF_B, (const void*)g_chsw, BTILE, smb + OFF_MBAR);
    }

    if (tid < TILE_M) {
        res[tid] = ~0ull;
        rowmin[tid] = 0xFFFFFFFFu;
    }
    if (tid == 1024 - 1) *qn = 0;
    if (tid < VQ) csq_s[tid] = g_csq[tid];

    // A: latents[b][d][t0+t] -> bf16 swizzled tile + fp32 copy
    {
        const float* xg = latents + (size_t)b * DQ * TQ + t0;
        for (int idx = tid; idx < DQ * TILE_M; idx += NTHREADS) {
            int d = idx >> 7;
            int t = idx & 127;     // coalesced over t
            float x = xg[(size_t)d * TQ + t];
            *(__nv_bfloat16*)(sm + OFF_AH + tswz(t, d)) = __float2bfloat16(x);
            Af[t * AF_STRIDE + d] = x;
        }
    }
    __syncthreads();   // A tile + mbarrier init visible to all

    // Per-thread ldmatrix constants (addressing validated R5-R16)
    const int arow_in16 = lane & 15;
    const int kca = lane >> 4;
    const int brow_in16 = (lane & 7) | ((lane >> 4) << 3);
    const int kcb = (lane >> 3) & 1;

    const int arow = warp_m * 16 + arow_in16;
    const int axr = arow & 7;
    const uint32_t abase = (uint32_t)(arow * 256);

    int bxr[2];
    uint32_t bbase[2];
#pragma unroll
    for (int n4 = 0; n4 < 2; n4++) {
        int row = warp_n * 32 + n4 * 16 + brow_in16;
        bxr[n4] = row & 7;
        bbase[n4] = (uint32_t)(row * 256);
    }

    for (int vc = 0; vc < NCHUNK; vc++) {
        const int v0 = vc * TILE_N;
        const int buf = vc & 1;

        // Wait for chunk vc's bulk copy, then a CTA barrier: after it, all
        // threads have finished chunk vc-1 compute -> buffer buf^1 is free.
        MBARRIER_WAIT_PARITY(smb + OFF_MBAR + buf * 8, (vc >> 1) & 1);
        __syncthreads();

        // Issue bulk load of chunk vc+1 into the other buffer
        if (tid == 0 && vc + 1 < NCHUNK) {
            uint32_t mb = smb + OFF_MBAR + (buf ^ 1) * 8;
            MBARRIER_EXPECT_TX(mb, BTILE);
            BULK_LOAD(smb + OFF_B + (buf ^ 1) * BTILE,
                      (const void*)(g_chsw + (size_t)(vc + 1) * BTILE),
                      BTILE, mb);
        }

        float acc[4][4];
#pragma unroll
        for (int ni = 0; ni < 4; ni++)
#pragma unroll
            for (int q = 0; q < 4; q++) acc[ni][q] = 0.f;

        const uint32_t bsm = smb + OFF_B + buf * BTILE;
#pragma unroll
        for (int ks = 0; ks < 8; ks++) {
            uint32_t aH[4];
            {
                uint32_t co = (uint32_t)((((ks << 1) | kca) ^ axr) << 4);
                LDMX4(aH, smb + OFF_AH + abase + co);
            }
            uint32_t bH[4][2];
#pragma unroll
            for (int n4 = 0; n4 < 2; n4++) {
                uint32_t co = (uint32_t)((((ks << 1) | kcb) ^ bxr[n4]) << 4);
                uint32_t r[4];
                LDMX4(r, bsm + bbase[n4] + co);
                bH[n4 * 2][0] = r[0]; bH[n4 * 2][1] = r[1];
                bH[n4 * 2 + 1][0] = r[2]; bH[n4 * 2 + 1][1] = r[3];
            }
#pragma unroll
            for (int ni = 0; ni < 4; ni++)
                mma_bf16(acc[ni], aH, bH[ni]);
        }

        // Convert acc -> cheap scores in place, track per-thread row mins
        float rm0 = 3.4e38f, rm1 = 3.4e38f;
#pragma unroll
        for (int ni = 0; ni < 4; ni++) {
            int col0 = v0 + warp_n * 32 + ni * 8 + (lane & 3) * 2;
            float cs0 = csq_s[col0], cs1 = csq_s[col0 + 1];
            float* c = acc[ni];
            c[0] = fmaf(-2.f, c[0], cs0);
            c[1] = fmaf(-2.f, c[1], cs1);
            c[2] = fmaf(-2.f, c[2], cs0);
            c[3] = fmaf(-2.f, c[3], cs1);
            rm0 = fminf(rm0, fminf(c[0], c[1]));
            rm1 = fminf(rm1, fminf(c[2], c[3]));
        }
        // rowmin monotone-decreasing: no barrier needed (stale read = safe
        // looser threshold; writer of true min reads its own update).
        {
            int row = warp_m * 16 + (lane >> 2);
            atomicMin(&rowmin[row], fford(rm0));
            atomicMin(&rowmin[row + 8], fford(rm1));
        }

        // Insert candidates within MARGIN of running row min
        {
            int rA = warp_m * 16 + (lane >> 2);
            float thA = fford_inv(rowmin[rA]) + MARGIN;
            float thB = fford_inv(rowmin[rA + 8]) + MARGIN;
#pragma unroll
            for (int ni = 0; ni < 4; ni++) {
                int col0 = v0 + warp_n * 32 + ni * 8 + (lane & 3) * 2;
                const float* c = acc[ni];
                if (c[0] <= thA) {
                    unsigned k = atomicAdd(qn, 1u);
                    if (k < QCAP) queue[k] = ((unsigned)rA << 10) | col0;
                }
                if (c[1] <= thA) {
                    unsigned k = atomicAdd(qn, 1u);
                    if (k < QCAP) queue[k] = ((unsigned)rA << 10) | (col0 + 1);
                }
                if (c[2] <= thB) {
                    unsigned k = atomicAdd(qn, 1u);
                    if (k < QCAP) queue[k] = ((unsigned)(rA + 8) << 10) | col0;
                }
                if (c[3] <= thB) {
                    unsigned k = atomicAdd(qn, 1u);
                    if (k < QCAP)
                        queue[k] = ((unsigned)(rA + 8) << 10) | (col0 + 1);
                }
            }
        }
    }
    __syncthreads();

    // Exact fp32 rescore of candidates: one warp per queue entry
    {
        unsigned n = *qn;
        if (n > QCAP) n = QCAP;
        for (unsigned e = wid; e < n; e += 32) {
            unsigned ent = queue[e];
            int r = ent >> 10;
            int v = ent & 1023;
            const float4 xa = *(const float4*)(Af + r * AF_STRIDE + lane * 4);
            const float4 ca = *(const float4*)(cb + (size_t)v * DQ + lane * 4);
            float s = xa.x * ca.x + xa.y * ca.y + xa.z * ca.z + xa.w * ca.w;
#pragma unroll
            for (int off = 16; off; off >>= 1)
                s += __shfl_down_sync(0xffffffffu, s, off);
            if (lane == 0) {
                float score = fmaf(-2.f, s, csq_s[v]);
                unsigned long long pk =
                    ((unsigned long long)fford(score) << 32) | (unsigned)v;
                atomicMin(&res[r], pk);
            }
        }
    }
    __syncthreads();

    // Write codes (as float) and fused quantized gather
    if (tid < TILE_M)
        codes[(size_t)b * TQ + t0 + tid] = (float)(unsigned)(res[tid] & 1023u);

    {
        int t = tid & 127;
        int dh = tid >> 7;                 // 0..7: d-eighths (16 each)
        int v = (int)(res[t] & 1023u);
        const float* crow = cb + (size_t)v * DQ + dh * 16;
        float* q = quant + (size_t)b * DQ * TQ + (size_t)(dh * 16) * TQ + t0 + t;
#pragma unroll
        for (int i = 0; i < 4; i++) {
            float4 c4 = *(const float4*)(crow + i * 4);
            q[(i * 4 + 0) * TQ] = c4.x;
            q[(i * 4 + 1) * TQ] = c4.y;
            q[(i * 4 + 2) * TQ] = c4.z;
            q[(i * 4 + 3) * TQ] = c4.w;
        }
    }
}

// ---------------------------------------------------------------------------
extern "C" void kernel_launch(void* const* d_in, const int* in_sizes, int n_in,
                              void* d_out, int out_size) {
    const float* latents = (const float*)d_in[0];   // (B, D, T) fp32
    const float* codebook = (const float*)d_in[1];  // (V, D)    fp32

    float* codes = (float*)d_out;             // B*T floats
    float* quant = (float*)d_out + BQ * TQ;   // B*D*T floats

    cudaFuncSetAttribute(vq_kernel,
                         cudaFuncAttributeMaxDynamicSharedMemorySize,
                         SMEM_TOTAL);

    prep_kernel<<<(VQ * 32) / 256, 256>>>(codebook);

    dim3 grid(TQ / TILE_M, BQ);   // (32, 16) = 512 blocks
    vq_kernel<<<grid, NTHREADS, SMEM_TOTAL>>>(latents, codebook, codes, quant);
}